// round 4
// baseline (speedup 1.0000x reference)
#include <cuda_runtime.h>
#include <cuda_fp16.h>

#define N_USERS 40000
#define N_ITEMS 20000
#define NNZ     1000000
#define D       64
#define N_TOTAL (N_USERS + N_ITEMS)
#define EPS     1e-8f
#define SCAN_BLOCKS 20
#define SCAN_CHUNK  1000

// ---------------- device scratch ----------------
__device__ uint4 g_lin_u[N_ITEMS * 8];
__device__ uint4 g_lin_i[N_USERS * 8];
__device__ uint4 g_emb_u0[N_USERS * 8];
__device__ uint4 g_emb_u1[N_USERS * 8];
__device__ uint4 g_emb_i0[N_ITEMS * 8];
__device__ uint4 g_emb_i1[N_ITEMS * 8];
__device__ float g_inv_u[N_USERS];
__device__ float g_inv_i[N_ITEMS];
__device__ float g_w_u[NNZ];
__device__ float g_w_i[NNZ];
__device__ int2  g_pk_u[NNZ];
__device__ int2  g_pk_i[NNZ];
__device__ int   g_i_src_u[NNZ];
__device__ int   g_slot[NNZ];
__device__ int   g_u_ptr[N_USERS + 1];
__device__ int   g_i_ptr[N_ITEMS + 1];
__device__ int   g_i_cnt[N_ITEMS];
__device__ int   g_part[SCAN_BLOCKS];

// ---------------- helpers ----------------
__device__ __forceinline__ void acc8(float2& a0, float2& a1, float2& a2, float2& a3,
                                     uint4 v, float w) {
    float2 b;
    b = __half22float2(*(__half2*)&v.x); a0.x = fmaf(w, b.x, a0.x); a0.y = fmaf(w, b.y, a0.y);
    b = __half22float2(*(__half2*)&v.y); a1.x = fmaf(w, b.x, a1.x); a1.y = fmaf(w, b.y, a1.y);
    b = __half22float2(*(__half2*)&v.z); a2.x = fmaf(w, b.x, a2.x); a2.y = fmaf(w, b.y, a2.y);
    b = __half22float2(*(__half2*)&v.w); a3.x = fmaf(w, b.x, a3.x); a3.y = fmaf(w, b.y, a3.y);
}
__device__ __forceinline__ uint4 pack8(float2 a0, float2 a1, float2 a2, float2 a3) {
    uint4 r;
    *(__half2*)&r.x = __floats2half2_rn(a0.x, a0.y);
    *(__half2*)&r.y = __floats2half2_rn(a1.x, a1.y);
    *(__half2*)&r.z = __floats2half2_rn(a2.x, a2.y);
    *(__half2*)&r.w = __floats2half2_rn(a3.x, a3.y);
    return r;
}
__device__ __forceinline__ void xor_reduce_groups(float2& a0, float2& a1, float2& a2, float2& a3) {
    #pragma unroll
    for (int o = 8; o <= 16; o <<= 1) {
        a0.x += __shfl_xor_sync(0xffffffffu, a0.x, o);
        a0.y += __shfl_xor_sync(0xffffffffu, a0.y, o);
        a1.x += __shfl_xor_sync(0xffffffffu, a1.x, o);
        a1.y += __shfl_xor_sync(0xffffffffu, a1.y, o);
        a2.x += __shfl_xor_sync(0xffffffffu, a2.x, o);
        a2.y += __shfl_xor_sync(0xffffffffu, a2.y, o);
        a3.x += __shfl_xor_sync(0xffffffffu, a3.x, o);
        a3.y += __shfl_xor_sync(0xffffffffu, a3.y, o);
    }
}

// ---------------- K1: zero counts + user CSR ptr + fp16 conversion ----------------
__global__ void k_setup(const int* __restrict__ u_idx,
                        const float* __restrict__ user_linear,
                        const float* __restrict__ item_linear) {
    int t = blockIdx.x * blockDim.x + threadIdx.x;
    if (t < N_ITEMS) g_i_cnt[t] = 0;
    if (t <= N_USERS) {
        int lo = 0, hi = NNZ;
        while (lo < hi) { int mid = (lo + hi) >> 1; if (u_idx[mid] < t) lo = mid + 1; else hi = mid; }
        g_u_ptr[t] = lo;
    }
    const int NU = N_ITEMS * 8;
    const int NI = N_USERS * 8;
    if (t < NU) {
        const float4* s = (const float4*)user_linear;
        float4 x0 = s[2 * t], x1 = s[2 * t + 1];
        g_lin_u[t] = pack8(make_float2(x0.x, x0.y), make_float2(x0.z, x0.w),
                           make_float2(x1.x, x1.y), make_float2(x1.z, x1.w));
    } else if (t < NU + NI) {
        int k = t - NU;
        const float4* s = (const float4*)item_linear;
        float4 x0 = s[2 * k], x1 = s[2 * k + 1];
        g_lin_i[k] = pack8(make_float2(x0.x, x0.y), make_float2(x0.z, x0.w),
                           make_float2(x1.x, x1.y), make_float2(x1.z, x1.w));
    }
}

__global__ void k_count(const int* __restrict__ i_idx) {
    int e = blockIdx.x * blockDim.x + threadIdx.x;
    if (e < NNZ) atomicAdd(&g_i_cnt[i_idx[e]], 1);
}

__global__ void __launch_bounds__(256) k_part() {
    __shared__ int wsum[8];
    int b = blockIdx.x, tid = threadIdx.x;
    int s = 0;
    for (int k = tid; k < SCAN_CHUNK; k += 256) s += g_i_cnt[b * SCAN_CHUNK + k];
    #pragma unroll
    for (int o = 16; o; o >>= 1) s += __shfl_xor_sync(0xffffffffu, s, o);
    if ((tid & 31) == 0) wsum[tid >> 5] = s;
    __syncthreads();
    if (tid < 8) {
        int x = wsum[tid];
        #pragma unroll
        for (int o = 4; o; o >>= 1) x += __shfl_xor_sync(0xffu, x, o);
        if (tid == 0) g_part[b] = x;
    }
}

__global__ void __launch_bounds__(1024) k_blkscan() {
    __shared__ int wsum[32];
    __shared__ int base_s;
    int b = blockIdx.x, tid = threadIdx.x, lane = tid & 31, wid = tid >> 5;
    if (tid == 0) {
        int base = 0;
        #pragma unroll
        for (int k = 0; k < SCAN_BLOCKS; ++k) if (k < b) base += g_part[k];
        base_s = base;
    }
    int idx = b * SCAN_CHUNK + tid;
    int x = (tid < SCAN_CHUNK) ? g_i_cnt[idx] : 0;
    int t = x;
    #pragma unroll
    for (int o = 1; o < 32; o <<= 1) { int y = __shfl_up_sync(0xffffffffu, t, o); if (lane >= o) t += y; }
    if (lane == 31) wsum[wid] = t;
    __syncthreads();
    if (wid == 0) {
        int s = wsum[lane];
        #pragma unroll
        for (int o = 1; o < 32; o <<= 1) { int y = __shfl_up_sync(0xffffffffu, s, o); if (lane >= o) s += y; }
        wsum[lane] = s;
    }
    __syncthreads();
    int incl = t + (wid ? wsum[wid - 1] : 0);
    if (tid < SCAN_CHUNK) {
        g_i_ptr[idx] = base_s + incl - x;
        g_i_cnt[idx] = 0;
    }
    if (b == SCAN_BLOCKS - 1 && tid == 0) g_i_ptr[N_ITEMS] = NNZ;
}

__global__ void k_scatter(const int* __restrict__ u_idx, const int* __restrict__ i_idx) {
    int e = blockIdx.x * blockDim.x + threadIdx.x;
    if (e >= NNZ) return;
    int i = i_idx[e];
    int pos = g_i_ptr[i] + atomicAdd(&g_i_cnt[i], 1);
    g_i_src_u[pos] = u_idx[e];
    g_slot[e] = pos;
}

// ---------------- base embeddings (warp per row, unrolled x2) ----------------
__global__ void __launch_bounds__(256) k_emb(const int* __restrict__ i_idx,
                                             float* __restrict__ out) {
    int r = (blockIdx.x * blockDim.x + threadIdx.x) >> 5;
    if (r >= N_TOTAL) return;
    int lane = threadIdx.x & 31, g = lane >> 3, c = lane & 7;
    const uint4* __restrict__ src;
    const int* __restrict__ idxarr;
    int beg, end, row;
    if (r < N_USERS) {
        row = r; src = g_lin_u; idxarr = i_idx;
        beg = g_u_ptr[r]; end = g_u_ptr[r + 1];
    } else {
        row = r - N_USERS; src = g_lin_i; idxarr = g_i_src_u;
        beg = g_i_ptr[row]; end = g_i_ptr[row + 1];
    }
    float2 a0 = {0,0}, a1 = {0,0}, a2 = {0,0}, a3 = {0,0};
    for (int ch = beg; ch < end; ch += 8) {
        int e0 = ch + g, e1 = ch + 4 + g;
        bool v0 = e0 < end, v1 = e1 < end;
        int idx0 = v0 ? idxarr[e0] : 0;
        int idx1 = v1 ? idxarr[e1] : 0;
        uint4 x0 = src[idx0 * 8 + c];
        uint4 x1 = src[idx1 * 8 + c];
        acc8(a0, a1, a2, a3, x0, v0 ? 1.0f : 0.0f);
        acc8(a0, a1, a2, a3, x1, v1 ? 1.0f : 0.0f);
    }
    xor_reduce_groups(a0, a1, a2, a3);
    float ss = a0.x*a0.x + a0.y*a0.y + a1.x*a1.x + a1.y*a1.y
             + a2.x*a2.x + a2.y*a2.y + a3.x*a3.x + a3.y*a3.y;
    #pragma unroll
    for (int o = 1; o <= 4; o <<= 1) ss += __shfl_xor_sync(0xffffffffu, ss, o);
    if (lane == 0) {
        float inv = 1.0f / fmaxf(sqrtf(ss), EPS);
        if (r < N_USERS) g_inv_u[row] = inv; else g_inv_i[row] = inv;
    }
    if (g == 0) {
        if (r < N_USERS) g_emb_u0[row * 8 + c] = pack8(a0, a1, a2, a3);
        else             g_emb_i0[row * 8 + c] = pack8(a0, a1, a2, a3);
        float4* o = (float4*)(out + (size_t)r * D + c * 8);
        o[0] = make_float4(a0.x, a0.y, a1.x, a1.y);
        o[1] = make_float4(a2.x, a2.y, a3.x, a3.y);
    }
}

// ---------------- weights + u-side norm + packing (warp per user, unrolled x2) ----------------
__global__ void __launch_bounds__(256) k_weights(const int* __restrict__ i_idx) {
    int u = (blockIdx.x * blockDim.x + threadIdx.x) >> 5;
    if (u >= N_USERS) return;
    int lane = threadIdx.x & 31, g = lane >> 3, c = lane & 7;
    int beg = g_u_ptr[u], end = g_u_ptr[u + 1];
    uint4 av = g_emb_u0[u * 8 + c];
    float2 A0 = __half22float2(*(__half2*)&av.x);
    float2 A1 = __half22float2(*(__half2*)&av.y);
    float2 A2 = __half22float2(*(__half2*)&av.z);
    float2 A3 = __half22float2(*(__half2*)&av.w);
    float invu = g_inv_u[u];
    float sum = 0.f;
    for (int ch = beg; ch < end; ch += 8) {
        int e0 = ch + g, e1 = ch + 4 + g;
        bool v0 = e0 < end, v1 = e1 < end;
        int i0 = v0 ? i_idx[e0] : 0;
        int i1 = v1 ? i_idx[e1] : 0;
        uint4 b0 = g_emb_i0[i0 * 8 + c];
        uint4 b1 = g_emb_i0[i1 * 8 + c];
        float2 b;
        float d0 = 0.f, d1 = 0.f;
        b = __half22float2(*(__half2*)&b0.x); d0 = fmaf(A0.x, b.x, d0); d0 = fmaf(A0.y, b.y, d0);
        b = __half22float2(*(__half2*)&b0.y); d0 = fmaf(A1.x, b.x, d0); d0 = fmaf(A1.y, b.y, d0);
        b = __half22float2(*(__half2*)&b0.z); d0 = fmaf(A2.x, b.x, d0); d0 = fmaf(A2.y, b.y, d0);
        b = __half22float2(*(__half2*)&b0.w); d0 = fmaf(A3.x, b.x, d0); d0 = fmaf(A3.y, b.y, d0);
        b = __half22float2(*(__half2*)&b1.x); d1 = fmaf(A0.x, b.x, d1); d1 = fmaf(A0.y, b.y, d1);
        b = __half22float2(*(__half2*)&b1.y); d1 = fmaf(A1.x, b.x, d1); d1 = fmaf(A1.y, b.y, d1);
        b = __half22float2(*(__half2*)&b1.z); d1 = fmaf(A2.x, b.x, d1); d1 = fmaf(A2.y, b.y, d1);
        b = __half22float2(*(__half2*)&b1.w); d1 = fmaf(A3.x, b.x, d1); d1 = fmaf(A3.y, b.y, d1);
        #pragma unroll
        for (int o = 1; o <= 4; o <<= 1) {
            d0 += __shfl_xor_sync(0xffffffffu, d0, o);
            d1 += __shfl_xor_sync(0xffffffffu, d1, o);
        }
        if (c == 0) {
            if (v0) {
                float s = d0 * invu * g_inv_i[i0];
                float w = fmaf(s, 0.5f, 0.5f);
                g_w_u[e0] = w; g_w_i[g_slot[e0]] = w; sum += w;
            }
            if (v1) {
                float s = d1 * invu * g_inv_i[i1];
                float w = fmaf(s, 0.5f, 0.5f);
                g_w_u[e1] = w; g_w_i[g_slot[e1]] = w; sum += w;
            }
        }
    }
    sum += __shfl_xor_sync(0xffffffffu, sum, 8);
    sum += __shfl_xor_sync(0xffffffffu, sum, 16);
    float invd = 1.0f / (sum + 1e-7f);
    invd = __shfl_sync(0xffffffffu, invd, 0);
    __syncwarp();
    __threadfence_block();
    for (int e = beg + lane; e < end; e += 32)
        g_pk_u[e] = make_int2(i_idx[e], __float_as_int(g_w_u[e] * invd));
}

// ---------------- i-side norm + packing ----------------
__global__ void k_norm_i() {
    int i = (blockIdx.x * blockDim.x + threadIdx.x) >> 5;
    if (i >= N_ITEMS) return;
    int lane = threadIdx.x & 31;
    int beg = g_i_ptr[i], end = g_i_ptr[i + 1];
    float s = 0.f;
    for (int p = beg + lane; p < end; p += 32) s += g_w_i[p];
    #pragma unroll
    for (int o = 16; o; o >>= 1) s += __shfl_xor_sync(0xffffffffu, s, o);
    float invd = 1.0f / (s + 1e-7f);
    for (int p = beg + lane; p < end; p += 32)
        g_pk_i[p] = make_int2(g_i_src_u[p], __float_as_int(g_w_i[p] * invd));
}

// ---------------- fused propagation layer (unrolled x2) ----------------
__global__ void __launch_bounds__(256) k_prop(float* __restrict__ out, int flip, float scale) {
    int r = (blockIdx.x * blockDim.x + threadIdx.x) >> 5;
    if (r >= N_TOTAL) return;
    int lane = threadIdx.x & 31, g = lane >> 3, c = lane & 7;
    const int2* __restrict__ pk;
    const uint4* __restrict__ src;
    uint4* __restrict__ dst;
    int beg, end, row;
    if (r < N_USERS) {
        row = r; pk = g_pk_u;
        src = flip ? g_emb_i1 : g_emb_i0;
        dst = flip ? g_emb_u0 : g_emb_u1;
        beg = g_u_ptr[r]; end = g_u_ptr[r + 1];
    } else {
        row = r - N_USERS; pk = g_pk_i;
        src = flip ? g_emb_u1 : g_emb_u0;
        dst = flip ? g_emb_i0 : g_emb_i1;
        beg = g_i_ptr[row]; end = g_i_ptr[row + 1];
    }
    float2 a0 = {0,0}, a1 = {0,0}, a2 = {0,0}, a3 = {0,0};
    for (int ch = beg; ch < end; ch += 8) {
        int e0 = ch + g, e1 = ch + 4 + g;
        int2 p0 = (e0 < end) ? pk[e0] : make_int2(0, 0);
        int2 p1 = (e1 < end) ? pk[e1] : make_int2(0, 0);
        uint4 x0 = src[p0.x * 8 + c];
        uint4 x1 = src[p1.x * 8 + c];
        acc8(a0, a1, a2, a3, x0, __int_as_float(p0.y));
        acc8(a0, a1, a2, a3, x1, __int_as_float(p1.y));
    }
    xor_reduce_groups(a0, a1, a2, a3);
    if (g == 0) {
        dst[row * 8 + c] = pack8(a0, a1, a2, a3);
        float4* o = (float4*)(out + (size_t)r * D + c * 8);
        float4 o0 = o[0], o1 = o[1];
        o0.x = (o0.x + a0.x) * scale; o0.y = (o0.y + a0.y) * scale;
        o0.z = (o0.z + a1.x) * scale; o0.w = (o0.w + a1.y) * scale;
        o1.x = (o1.x + a2.x) * scale; o1.y = (o1.y + a2.y) * scale;
        o1.z = (o1.z + a3.x) * scale; o1.w = (o1.w + a3.y) * scale;
        o[0] = o0; o[1] = o1;
    }
}

// ---------------- launch ----------------
extern "C" void kernel_launch(void* const* d_in, const int* in_sizes, int n_in,
                              void* d_out, int out_size) {
    const float* user_linear = (const float*)d_in[0];
    const float* item_linear = (const float*)d_in[1];
    const int*   u_idx       = (const int*)d_in[2];
    const int*   i_idx       = (const int*)d_in[3];
    float* out = (float*)d_out;

    int setup_threads = (N_USERS + N_ITEMS) * 8;  // covers all roles
    k_setup<<<(setup_threads + 255) / 256, 256>>>(u_idx, user_linear, item_linear);
    k_count<<<(NNZ + 255) / 256, 256>>>(i_idx);
    k_part<<<SCAN_BLOCKS, 256>>>();
    k_blkscan<<<SCAN_BLOCKS, 1024>>>();
    k_scatter<<<(NNZ + 255) / 256, 256>>>(u_idx, i_idx);

    k_emb<<<(N_TOTAL * 32 + 255) / 256, 256>>>(i_idx, out);
    k_weights<<<(N_USERS * 32 + 255) / 256, 256>>>(i_idx);
    k_norm_i<<<(N_ITEMS * 32 + 255) / 256, 256>>>();

    k_prop<<<(N_TOTAL * 32 + 255) / 256, 256>>>(out, 0, 1.0f);
    k_prop<<<(N_TOTAL * 32 + 255) / 256, 256>>>(out, 1, 1.0f);
    k_prop<<<(N_TOTAL * 32 + 255) / 256, 256>>>(out, 0, 0.25f);
}

// round 5
// speedup vs baseline: 1.0265x; 1.0265x over previous
#include <cuda_runtime.h>
#include <cuda_fp16.h>

#define N_USERS 40000
#define N_ITEMS 20000
#define NNZ     1000000
#define D       64
#define N_TOTAL (N_USERS + N_ITEMS)
#define EPS     1e-8f
#define SCAN_BLOCKS 20
#define SCAN_CHUNK  1000

// ---------------- device scratch ----------------
__device__ uint4 g_lin_u[N_ITEMS * 8];
__device__ uint4 g_lin_i[N_USERS * 8];
__device__ uint4 g_emb_u0[N_USERS * 8];
__device__ uint4 g_emb_u1[N_USERS * 8];
__device__ uint4 g_emb_i0[N_ITEMS * 8];
__device__ uint4 g_emb_i1[N_ITEMS * 8];
__device__ float g_inv_u[N_USERS];
__device__ float g_inv_i[N_ITEMS];
__device__ float g_w_u[NNZ];
__device__ float g_w_i[NNZ];
__device__ int2  g_pk_u[NNZ];
__device__ int2  g_pk_i[NNZ];
__device__ int   g_i_src_u[NNZ];
__device__ int   g_slot[NNZ];
__device__ int   g_u_ptr[N_USERS + 1];
__device__ int   g_i_ptr[N_ITEMS + 1];
__device__ int   g_i_cnt[N_ITEMS];
__device__ int   g_part[SCAN_BLOCKS];

// ---------------- helpers ----------------
__device__ __forceinline__ void acc8(float2& a0, float2& a1, float2& a2, float2& a3,
                                     uint4 v, float w) {
    float2 b;
    b = __half22float2(*(__half2*)&v.x); a0.x = fmaf(w, b.x, a0.x); a0.y = fmaf(w, b.y, a0.y);
    b = __half22float2(*(__half2*)&v.y); a1.x = fmaf(w, b.x, a1.x); a1.y = fmaf(w, b.y, a1.y);
    b = __half22float2(*(__half2*)&v.z); a2.x = fmaf(w, b.x, a2.x); a2.y = fmaf(w, b.y, a2.y);
    b = __half22float2(*(__half2*)&v.w); a3.x = fmaf(w, b.x, a3.x); a3.y = fmaf(w, b.y, a3.y);
}
__device__ __forceinline__ uint4 pack8(float2 a0, float2 a1, float2 a2, float2 a3) {
    uint4 r;
    *(__half2*)&r.x = __floats2half2_rn(a0.x, a0.y);
    *(__half2*)&r.y = __floats2half2_rn(a1.x, a1.y);
    *(__half2*)&r.z = __floats2half2_rn(a2.x, a2.y);
    *(__half2*)&r.w = __floats2half2_rn(a3.x, a3.y);
    return r;
}
__device__ __forceinline__ void xor_reduce_groups(float2& a0, float2& a1, float2& a2, float2& a3) {
    #pragma unroll
    for (int o = 8; o <= 16; o <<= 1) {
        a0.x += __shfl_xor_sync(0xffffffffu, a0.x, o);
        a0.y += __shfl_xor_sync(0xffffffffu, a0.y, o);
        a1.x += __shfl_xor_sync(0xffffffffu, a1.x, o);
        a1.y += __shfl_xor_sync(0xffffffffu, a1.y, o);
        a2.x += __shfl_xor_sync(0xffffffffu, a2.x, o);
        a2.y += __shfl_xor_sync(0xffffffffu, a2.y, o);
        a3.x += __shfl_xor_sync(0xffffffffu, a3.x, o);
        a3.y += __shfl_xor_sync(0xffffffffu, a3.y, o);
    }
}
__device__ __forceinline__ void store_out(float* __restrict__ out, int r, int c,
                                          float2 a0, float2 a1, float2 a2, float2 a3,
                                          float scale) {
    float4* o = (float4*)(out + (size_t)r * D + c * 8);
    float4 o0 = o[0], o1 = o[1];
    o0.x = (o0.x + a0.x) * scale; o0.y = (o0.y + a0.y) * scale;
    o0.z = (o0.z + a1.x) * scale; o0.w = (o0.w + a1.y) * scale;
    o1.x = (o1.x + a2.x) * scale; o1.y = (o1.y + a2.y) * scale;
    o1.z = (o1.z + a3.x) * scale; o1.w = (o1.w + a3.y) * scale;
    o[0] = o0; o[1] = o1;
}

// ---------------- K1: zero counts + user CSR ptr + fp16 conversion ----------------
__global__ void k_setup(const int* __restrict__ u_idx,
                        const float* __restrict__ user_linear,
                        const float* __restrict__ item_linear) {
    int t = blockIdx.x * blockDim.x + threadIdx.x;
    if (t < N_ITEMS) g_i_cnt[t] = 0;
    if (t <= N_USERS) {
        int lo = 0, hi = NNZ;
        while (lo < hi) { int mid = (lo + hi) >> 1; if (u_idx[mid] < t) lo = mid + 1; else hi = mid; }
        g_u_ptr[t] = lo;
    }
    const int NU = N_ITEMS * 8;
    const int NI = N_USERS * 8;
    if (t < NU) {
        const float4* s = (const float4*)user_linear;
        float4 x0 = s[2 * t], x1 = s[2 * t + 1];
        g_lin_u[t] = pack8(make_float2(x0.x, x0.y), make_float2(x0.z, x0.w),
                           make_float2(x1.x, x1.y), make_float2(x1.z, x1.w));
    } else if (t < NU + NI) {
        int k = t - NU;
        const float4* s = (const float4*)item_linear;
        float4 x0 = s[2 * k], x1 = s[2 * k + 1];
        g_lin_i[k] = pack8(make_float2(x0.x, x0.y), make_float2(x0.z, x0.w),
                           make_float2(x1.x, x1.y), make_float2(x1.z, x1.w));
    }
}

__global__ void k_count(const int* __restrict__ i_idx) {
    int e = blockIdx.x * blockDim.x + threadIdx.x;
    if (e < NNZ) atomicAdd(&g_i_cnt[i_idx[e]], 1);
}

__global__ void __launch_bounds__(256) k_part() {
    __shared__ int wsum[8];
    int b = blockIdx.x, tid = threadIdx.x;
    int s = 0;
    for (int k = tid; k < SCAN_CHUNK; k += 256) s += g_i_cnt[b * SCAN_CHUNK + k];
    #pragma unroll
    for (int o = 16; o; o >>= 1) s += __shfl_xor_sync(0xffffffffu, s, o);
    if ((tid & 31) == 0) wsum[tid >> 5] = s;
    __syncthreads();
    if (tid < 8) {
        int x = wsum[tid];
        #pragma unroll
        for (int o = 4; o; o >>= 1) x += __shfl_xor_sync(0xffu, x, o);
        if (tid == 0) g_part[b] = x;
    }
}

__global__ void __launch_bounds__(1024) k_blkscan() {
    __shared__ int wsum[32];
    __shared__ int base_s;
    int b = blockIdx.x, tid = threadIdx.x, lane = tid & 31, wid = tid >> 5;
    if (tid == 0) {
        int base = 0;
        #pragma unroll
        for (int k = 0; k < SCAN_BLOCKS; ++k) if (k < b) base += g_part[k];
        base_s = base;
    }
    int idx = b * SCAN_CHUNK + tid;
    int x = (tid < SCAN_CHUNK) ? g_i_cnt[idx] : 0;
    int t = x;
    #pragma unroll
    for (int o = 1; o < 32; o <<= 1) { int y = __shfl_up_sync(0xffffffffu, t, o); if (lane >= o) t += y; }
    if (lane == 31) wsum[wid] = t;
    __syncthreads();
    if (wid == 0) {
        int s = wsum[lane];
        #pragma unroll
        for (int o = 1; o < 32; o <<= 1) { int y = __shfl_up_sync(0xffffffffu, s, o); if (lane >= o) s += y; }
        wsum[lane] = s;
    }
    __syncthreads();
    int incl = t + (wid ? wsum[wid - 1] : 0);
    if (tid < SCAN_CHUNK) {
        g_i_ptr[idx] = base_s + incl - x;
        g_i_cnt[idx] = 0;
    }
    if (b == SCAN_BLOCKS - 1 && tid == 0) g_i_ptr[N_ITEMS] = NNZ;
}

__global__ void k_scatter(const int* __restrict__ u_idx, const int* __restrict__ i_idx) {
    int e = blockIdx.x * blockDim.x + threadIdx.x;
    if (e >= NNZ) return;
    int i = i_idx[e];
    int pos = g_i_ptr[i] + atomicAdd(&g_i_cnt[i], 1);
    g_i_src_u[pos] = u_idx[e];
    g_slot[e] = pos;
}

// ---------------- base embeddings (warp per row) ----------------
__global__ void __launch_bounds__(256) k_emb(const int* __restrict__ i_idx,
                                             float* __restrict__ out) {
    int r = (blockIdx.x * blockDim.x + threadIdx.x) >> 5;
    if (r >= N_TOTAL) return;
    int lane = threadIdx.x & 31, g = lane >> 3, c = lane & 7;
    const uint4* __restrict__ src;
    const int* __restrict__ idxarr;
    int beg, end, row;
    if (r < N_USERS) {
        row = r; src = g_lin_u; idxarr = i_idx;
        beg = g_u_ptr[r]; end = g_u_ptr[r + 1];
    } else {
        row = r - N_USERS; src = g_lin_i; idxarr = g_i_src_u;
        beg = g_i_ptr[row]; end = g_i_ptr[row + 1];
    }
    float2 a0 = {0,0}, a1 = {0,0}, a2 = {0,0}, a3 = {0,0};
    for (int ch = beg; ch < end; ch += 4) {
        int e = ch + g;
        bool val = e < end;
        int idx = val ? idxarr[e] : 0;
        uint4 v = src[idx * 8 + c];
        acc8(a0, a1, a2, a3, v, val ? 1.0f : 0.0f);
    }
    xor_reduce_groups(a0, a1, a2, a3);
    float ss = a0.x*a0.x + a0.y*a0.y + a1.x*a1.x + a1.y*a1.y
             + a2.x*a2.x + a2.y*a2.y + a3.x*a3.x + a3.y*a3.y;
    #pragma unroll
    for (int o = 1; o <= 4; o <<= 1) ss += __shfl_xor_sync(0xffffffffu, ss, o);
    if (lane == 0) {
        float inv = 1.0f / fmaxf(sqrtf(ss), EPS);
        if (r < N_USERS) g_inv_u[row] = inv; else g_inv_i[row] = inv;
    }
    if (g == 0) {
        if (r < N_USERS) g_emb_u0[row * 8 + c] = pack8(a0, a1, a2, a3);
        else             g_emb_i0[row * 8 + c] = pack8(a0, a1, a2, a3);
        float4* o = (float4*)(out + (size_t)r * D + c * 8);
        o[0] = make_float4(a0.x, a0.y, a1.x, a1.y);
        o[1] = make_float4(a2.x, a2.y, a3.x, a3.y);
    }
}

// ---- weights + u-norm + FUSED layer-1 user propagation + pk_u packing (warp per user) ----
__global__ void __launch_bounds__(256) k_weights(const int* __restrict__ i_idx,
                                                 float* __restrict__ out) {
    int u = (blockIdx.x * blockDim.x + threadIdx.x) >> 5;
    if (u >= N_USERS) return;
    int lane = threadIdx.x & 31, g = lane >> 3, c = lane & 7;
    int beg = g_u_ptr[u], end = g_u_ptr[u + 1];
    uint4 av = g_emb_u0[u * 8 + c];
    float2 A0 = __half22float2(*(__half2*)&av.x);
    float2 A1 = __half22float2(*(__half2*)&av.y);
    float2 A2 = __half22float2(*(__half2*)&av.z);
    float2 A3 = __half22float2(*(__half2*)&av.w);
    float invu = g_inv_u[u];
    float sum = 0.f;
    // pass 1: cosine weights
    for (int ch = beg; ch < end; ch += 4) {
        int e = ch + g;
        bool val = e < end;
        int i = val ? i_idx[e] : 0;
        uint4 bv = g_emb_i0[i * 8 + c];
        float2 b;
        float d = 0.f;
        b = __half22float2(*(__half2*)&bv.x); d = fmaf(A0.x, b.x, d); d = fmaf(A0.y, b.y, d);
        b = __half22float2(*(__half2*)&bv.y); d = fmaf(A1.x, b.x, d); d = fmaf(A1.y, b.y, d);
        b = __half22float2(*(__half2*)&bv.z); d = fmaf(A2.x, b.x, d); d = fmaf(A2.y, b.y, d);
        b = __half22float2(*(__half2*)&bv.w); d = fmaf(A3.x, b.x, d); d = fmaf(A3.y, b.y, d);
        #pragma unroll
        for (int o = 1; o <= 4; o <<= 1) d += __shfl_xor_sync(0xffffffffu, d, o);
        if (c == 0 && val) {
            float s = d * invu * g_inv_i[i];
            float w = fmaf(s, 0.5f, 0.5f);
            g_w_u[e] = w; g_w_i[g_slot[e]] = w; sum += w;
        }
    }
    sum += __shfl_xor_sync(0xffffffffu, sum, 8);
    sum += __shfl_xor_sync(0xffffffffu, sum, 16);
    float invd = 1.0f / (sum + 1e-7f);
    invd = __shfl_sync(0xffffffffu, invd, 0);
    __syncwarp();
    __threadfence_block();
    // pass 2: layer-1 user propagation over the same (L1-hot) item rows + pk_u packing
    float2 a0 = {0,0}, a1 = {0,0}, a2 = {0,0}, a3 = {0,0};
    for (int ch = beg; ch < end; ch += 4) {
        int e = ch + g;
        bool val = e < end;
        int i = val ? i_idx[e] : 0;
        float wn = val ? g_w_u[e] * invd : 0.0f;
        if (c == 0 && val) g_pk_u[e] = make_int2(i, __float_as_int(wn));
        uint4 v = g_emb_i0[i * 8 + c];
        acc8(a0, a1, a2, a3, v, wn);
    }
    xor_reduce_groups(a0, a1, a2, a3);
    if (g == 0) {
        g_emb_u1[u * 8 + c] = pack8(a0, a1, a2, a3);
        store_out(out, u, c, a0, a1, a2, a3, 1.0f);
    }
}

// ---- i-norm + FUSED layer-1 item propagation + pk_i packing (warp per item) ----
__global__ void __launch_bounds__(256) k_norm_i(float* __restrict__ out) {
    int i = (blockIdx.x * blockDim.x + threadIdx.x) >> 5;
    if (i >= N_ITEMS) return;
    int lane = threadIdx.x & 31, g = lane >> 3, c = lane & 7;
    int beg = g_i_ptr[i], end = g_i_ptr[i + 1];
    float s = 0.f;
    for (int p = beg + lane; p < end; p += 32) s += g_w_i[p];
    #pragma unroll
    for (int o = 16; o; o >>= 1) s += __shfl_xor_sync(0xffffffffu, s, o);
    float invd = 1.0f / (s + 1e-7f);
    float2 a0 = {0,0}, a1 = {0,0}, a2 = {0,0}, a3 = {0,0};
    for (int ch = beg; ch < end; ch += 4) {
        int p = ch + g;
        bool val = p < end;
        int uu = val ? g_i_src_u[p] : 0;
        float wn = val ? g_w_i[p] * invd : 0.0f;
        if (c == 0 && val) g_pk_i[p] = make_int2(uu, __float_as_int(wn));
        uint4 v = g_emb_u0[uu * 8 + c];
        acc8(a0, a1, a2, a3, v, wn);
    }
    xor_reduce_groups(a0, a1, a2, a3);
    if (g == 0) {
        g_emb_i1[i * 8 + c] = pack8(a0, a1, a2, a3);
        store_out(out, N_USERS + i, c, a0, a1, a2, a3, 1.0f);
    }
}

// ---------------- propagation layers 2,3 ----------------
__global__ void __launch_bounds__(256) k_prop(float* __restrict__ out, int flip, float scale) {
    int r = (blockIdx.x * blockDim.x + threadIdx.x) >> 5;
    if (r >= N_TOTAL) return;
    int lane = threadIdx.x & 31, g = lane >> 3, c = lane & 7;
    const int2* __restrict__ pk;
    const uint4* __restrict__ src;
    uint4* __restrict__ dst;
    int beg, end, row;
    if (r < N_USERS) {
        row = r; pk = g_pk_u;
        src = flip ? g_emb_i1 : g_emb_i0;
        dst = flip ? g_emb_u0 : g_emb_u1;
        beg = g_u_ptr[r]; end = g_u_ptr[r + 1];
    } else {
        row = r - N_USERS; pk = g_pk_i;
        src = flip ? g_emb_u1 : g_emb_u0;
        dst = flip ? g_emb_i0 : g_emb_i1;
        beg = g_i_ptr[row]; end = g_i_ptr[row + 1];
    }
    float2 a0 = {0,0}, a1 = {0,0}, a2 = {0,0}, a3 = {0,0};
    for (int ch = beg; ch < end; ch += 4) {
        int e = ch + g;
        int2 p = (e < end) ? pk[e] : make_int2(0, 0);
        uint4 v = src[p.x * 8 + c];
        acc8(a0, a1, a2, a3, v, __int_as_float(p.y));
    }
    xor_reduce_groups(a0, a1, a2, a3);
    if (g == 0) {
        dst[row * 8 + c] = pack8(a0, a1, a2, a3);
        store_out(out, r, c, a0, a1, a2, a3, scale);
    }
}

// ---------------- launch ----------------
extern "C" void kernel_launch(void* const* d_in, const int* in_sizes, int n_in,
                              void* d_out, int out_size) {
    const float* user_linear = (const float*)d_in[0];
    const float* item_linear = (const float*)d_in[1];
    const int*   u_idx       = (const int*)d_in[2];
    const int*   i_idx       = (const int*)d_in[3];
    float* out = (float*)d_out;

    int setup_threads = (N_USERS + N_ITEMS) * 8;
    k_setup<<<(setup_threads + 255) / 256, 256>>>(u_idx, user_linear, item_linear);
    k_count<<<(NNZ + 255) / 256, 256>>>(i_idx);
    k_part<<<SCAN_BLOCKS, 256>>>();
    k_blkscan<<<SCAN_BLOCKS, 1024>>>();
    k_scatter<<<(NNZ + 255) / 256, 256>>>(u_idx, i_idx);

    k_emb<<<(N_TOTAL * 32 + 255) / 256, 256>>>(i_idx, out);
    // fused: weights + u-norm + layer-1 user prop; then i-norm + layer-1 item prop
    k_weights<<<(N_USERS * 32 + 255) / 256, 256>>>(i_idx, out);
    k_norm_i<<<(N_ITEMS * 32 + 255) / 256, 256>>>(out);

    // layers 2, 3
    k_prop<<<(N_TOTAL * 32 + 255) / 256, 256>>>(out, 1, 1.0f);
    k_prop<<<(N_TOTAL * 32 + 255) / 256, 256>>>(out, 0, 0.25f);
}